// round 3
// baseline (speedup 1.0000x reference)
#include <cuda_runtime.h>
#include <cuda_bf16.h>
#include <math.h>

// reconstruction_loss: Charbonnier mean over MSFA-mosaic-gathered pixels.
//   X, Y: [B=8, C=16, H=512, W=512] fp32
//   out:  scalar = mean_{b,h,w} sqrt((X[b,c,h,w]-Y[b,c,h,w])^2 + 1e-6),
//         c = (h%4)*4 + (w%4)
//
// Memory-roofline design: only every 4th float of 1/4 of the channel rows is
// useful; sector granularity forces 4x-useful DRAM traffic = 64 MiB total.
// The (b,h,w)-linear indexing below touches exactly that minimum.

#define MAIN_BLOCKS 2048
#define MAIN_THREADS 256
#define TOTAL_PIX (8u * 512u * 512u)          // 2097152
#define STRIDE (MAIN_BLOCKS * MAIN_THREADS)   // 524288 -> exactly 4 iters/thread

__device__ float g_partial[MAIN_BLOCKS];

__global__ void __launch_bounds__(MAIN_THREADS)
msfa_charbonnier_main(const float* __restrict__ X, const float* __restrict__ Y) {
    unsigned tid = blockIdx.x * MAIN_THREADS + threadIdx.x;

    float acc = 0.0f;
#pragma unroll 4
    for (unsigned e = tid; e < TOTAL_PIX; e += STRIDE) {
        unsigned b = e >> 18;           // / (512*512)
        unsigned h = (e >> 9) & 511u;
        unsigned w = e & 511u;
        unsigned c = ((h & 3u) << 2) | (w & 3u);
        unsigned off = (((b << 4) | c) << 18) | (h << 9) | w;
        float d = __ldg(X + off) - __ldg(Y + off);
        acc += sqrtf(fmaf(d, d, 1e-6f));
    }

    // warp reduce
#pragma unroll
    for (int s = 16; s > 0; s >>= 1)
        acc += __shfl_xor_sync(0xffffffffu, acc, s);

    __shared__ float sm[MAIN_THREADS / 32];
    if ((threadIdx.x & 31u) == 0u)
        sm[threadIdx.x >> 5] = acc;
    __syncthreads();

    if (threadIdx.x < (MAIN_THREADS / 32)) {
        float v = sm[threadIdx.x];
#pragma unroll
        for (int s = (MAIN_THREADS / 64); s > 0; s >>= 1)
            v += __shfl_xor_sync(0xffu, v, s);
        if (threadIdx.x == 0)
            g_partial[blockIdx.x] = v;
    }
}

// Deterministic final reduction of 2048 block partials, single block.
__global__ void __launch_bounds__(1024)
msfa_charbonnier_finalize(float* __restrict__ out) {
    float v = g_partial[threadIdx.x] + g_partial[threadIdx.x + 1024];
#pragma unroll
    for (int s = 16; s > 0; s >>= 1)
        v += __shfl_xor_sync(0xffffffffu, v, s);

    __shared__ float sm[32];
    if ((threadIdx.x & 31u) == 0u)
        sm[threadIdx.x >> 5] = v;
    __syncthreads();

    if (threadIdx.x < 32) {
        float t = sm[threadIdx.x];
#pragma unroll
        for (int s = 16; s > 0; s >>= 1)
            t += __shfl_xor_sync(0xffffffffu, t, s);
        if (threadIdx.x == 0)
            out[0] = t * (1.0f / (float)TOTAL_PIX);
    }
}

extern "C" void kernel_launch(void* const* d_in, const int* in_sizes, int n_in,
                              void* d_out, int out_size) {
    const float* X = (const float*)d_in[0];
    const float* Y = (const float*)d_in[1];
    float* out = (float*)d_out;

    msfa_charbonnier_main<<<MAIN_BLOCKS, MAIN_THREADS>>>(X, Y);
    msfa_charbonnier_finalize<<<1, 1024>>>(out);
}